// round 11
// baseline (speedup 1.0000x reference)
#include <cuda_runtime.h>
#include <cuda_bf16.h>
#include <cstdint>

// Problem constants (match reference)
#define N_B   16
#define T_DIM 4096
#define F_DIM 256
#define PAD_MAX 1228                   // int(0.3 * 4096)
#define TP    (T_DIM + 2 * PAD_MAX)    // 6552

#define OUT_ELEMS (N_B * TP * F_DIM)   // 26,836,992

// Partition 1: source rows (read once, scatter to 1-3 dests), 2 rows/warp
// Partition 2: zero rows (no reads), 4 rows/warp, write-through stores
#define WARPS_PER_BLK  8
#define SRC_RPW        2
#define SRC_RPB        (SRC_RPW * WARPS_PER_BLK)                  // 16
#define SRC_BLOCKS     (T_DIM / SRC_RPB)                          // 256 (exact)
#define ZERO_RPW       4
#define ZERO_RPB       (ZERO_RPW * WARPS_PER_BLK)                 // 32
#define ZERO_BLOCKS    ((TP + ZERO_RPB - 1) / ZERO_RPB)           // 205
#define GRID_X         (SRC_BLOCKS + ZERO_BLOCKS)                 // 461

__global__ __launch_bounds__(256)
void random_shift_kernel(const float* __restrict__ in_,
                         const int*   __restrict__ in_lens,
                         const int*   __restrict__ pad,
                         float* __restrict__ out,
                         int tail_count)
{
    const int n    = blockIdx.y;
    const int w    = threadIdx.x >> 5;
    const int lane = threadIdx.x & 31;

    // warp-uniform metadata (L1 broadcast hits)
    const int lens = __ldg(&in_lens[n]);
    const int p0   = __ldg(&pad[n]);
    const int p1   = __ldg(&pad[N_B + n]);
    const int out_len = lens + p0 + p1;

    float* out_n = out + (size_t)n * TP * F_DIM;

    if (blockIdx.x < SRC_BLOCKS) {
        // ── scatter partition: each src row read ONCE, written to 1-3 dests ──
        // Valid output + input must stay L2-resident: normal (write-back) stores.
        const float* in_n = in_ + (size_t)n * T_DIM * F_DIM;
        const int s0 = blockIdx.x * SRC_RPB + w * SRC_RPW;

        bool act[SRC_RPW];
        const float4* sp[SRC_RPW];
        #pragma unroll
        for (int r = 0; r < SRC_RPW; r++) {
            int s = s0 + r;
            act[r] = (s < lens);
            sp[r]  = reinterpret_cast<const float4*>(in_n + (size_t)s * F_DIM) + lane;
        }

        float4 val[SRC_RPW][2];
        #pragma unroll
        for (int r = 0; r < SRC_RPW; r++) {
            #pragma unroll
            for (int h = 0; h < 2; h++) {
                val[r][h] = act[r] ? __ldg(sp[r] + h * 32)
                                   : make_float4(0.f, 0.f, 0.f, 0.f);
            }
        }

        #pragma unroll
        for (int r = 0; r < SRC_RPW; r++) {
            if (!act[r]) continue;
            int s = s0 + r;

            // mid: t = p0 + s  (always valid)
            {
                float4* op = reinterpret_cast<float4*>(out_n + (size_t)(p0 + s) * F_DIM) + lane;
                op[0]  = val[r][0];
                op[32] = val[r][1];
            }
            // left reflect: t = p0 - s, valid for 1 <= s <= p0
            if (s >= 1 && s <= p0) {
                float4* op = reinterpret_cast<float4*>(out_n + (size_t)(p0 - s) * F_DIM) + lane;
                op[0]  = val[r][0];
                op[32] = val[r][1];
            }
            // right reflect: t = 2*lens + p0 - 2 - s, valid for lens-p1-1 <= s <= lens-2
            if (s >= lens - p1 - 1 && s <= lens - 2) {
                float4* op = reinterpret_cast<float4*>(out_n + (size_t)(2 * lens + p0 - 2 - s) * F_DIM) + lane;
                op[0]  = val[r][0];
                op[32] = val[r][1];
            }
        }
    } else {
        // ── zero partition: t in [out_len, TP) ──
        // Write-through: never re-read, keep it OUT of L2 so the L2-resident
        // working set (input + valid output) fits under 126 MB.
        const int t0 = (blockIdx.x - SRC_BLOCKS) * ZERO_RPB + w * ZERO_RPW;
        const float4 z = make_float4(0.f, 0.f, 0.f, 0.f);
        #pragma unroll
        for (int r = 0; r < ZERO_RPW; r++) {
            int t = t0 + r;
            if (t < TP && t >= out_len) {
                float4* op = reinterpret_cast<float4*>(out_n + (size_t)t * F_DIM) + lane;
                __stwt(op,      z);
                __stwt(op + 32, z);
            }
        }
    }

    // Fold out_lens tail write into the first block (values exact in fp32).
    if (blockIdx.x == 0 && blockIdx.y == 0 && threadIdx.x < 16) {
        int ix = threadIdx.x;
        if (ix < tail_count) {
            int ol = __ldg(&in_lens[ix]) + __ldg(&pad[ix]) + __ldg(&pad[N_B + ix]);
            out[OUT_ELEMS + ix] = (float)ol;
        }
    }
}

extern "C" void kernel_launch(void* const* d_in, const int* in_sizes, int n_in,
                              void* d_out, int out_size)
{
    const float* in_  = (const float*)d_in[0];
    const int*   lens = (const int*)d_in[1];
    const int*   pad  = (const int*)d_in[2];
    float*       out  = (float*)d_out;

    int tail = out_size - OUT_ELEMS;   // out_lens packed after main tensor (if present)
    if (tail < 0) tail = 0;

    dim3 grid(GRID_X, N_B, 1);         // 461 x 16 = 7376 blocks
    random_shift_kernel<<<grid, 256>>>(in_, lens, pad, out, tail);
}

// round 12
// speedup vs baseline: 1.0890x; 1.0890x over previous
#include <cuda_runtime.h>
#include <cuda_bf16.h>
#include <cstdint>

// Problem constants (match reference)
#define N_B   16
#define T_DIM 4096
#define F_DIM 256
#define PAD_MAX 1228                   // int(0.3 * 4096)
#define TP    (T_DIM + 2 * PAD_MAX)    // 6552

#define OUT_ELEMS (N_B * TP * F_DIM)   // 26,836,992

// Partition 1: source rows (read once, scatter to 1-3 dests)
// Partition 2: zero rows (no reads)
#define ROWS_PER_WARP  2
#define WARPS_PER_BLK  8
#define ROWS_PER_BLK   (ROWS_PER_WARP * WARPS_PER_BLK)            // 16
#define SRC_BLOCKS     (T_DIM / ROWS_PER_BLK)                     // 256 (exact)
#define ZERO_BLOCKS    ((TP + ROWS_PER_BLK - 1) / ROWS_PER_BLK)   // 410
#define GRID_X         (SRC_BLOCKS + ZERO_BLOCKS)                 // 666

__global__ __launch_bounds__(256)
void random_shift_kernel(const float* __restrict__ in_,
                         const int*   __restrict__ in_lens,
                         const int*   __restrict__ pad,
                         float* __restrict__ out,
                         int tail_count)
{
    const int n    = blockIdx.y;
    const int w    = threadIdx.x >> 5;
    const int lane = threadIdx.x & 31;

    // warp-uniform metadata (L1 broadcast hits)
    const int lens = __ldg(&in_lens[n]);
    const int p0   = __ldg(&pad[n]);
    const int p1   = __ldg(&pad[N_B + n]);

    float* out_n = out + (size_t)n * TP * F_DIM;
    const int out_len = lens + p0 + p1;

    if (blockIdx.x < SRC_BLOCKS) {
        // ── scatter partition: each src row read ONCE, written to 1-3 dests ──
        const float* in_n = in_ + (size_t)n * T_DIM * F_DIM;
        const int s0 = blockIdx.x * ROWS_PER_BLK + w * ROWS_PER_WARP;

        bool act[ROWS_PER_WARP];
        const float4* sp[ROWS_PER_WARP];
        #pragma unroll
        for (int r = 0; r < ROWS_PER_WARP; r++) {
            int s = s0 + r;
            act[r] = (s < lens);
            sp[r]  = reinterpret_cast<const float4*>(in_n + (size_t)s * F_DIM) + lane;
        }

        // cached loads: input stays L2-resident across graph replays
        float4 val[ROWS_PER_WARP][2];
        #pragma unroll
        for (int r = 0; r < ROWS_PER_WARP; r++) {
            #pragma unroll
            for (int h = 0; h < 2; h++) {
                val[r][h] = act[r] ? __ldg(sp[r] + h * 32)
                                   : make_float4(0.f, 0.f, 0.f, 0.f);
            }
        }

        #pragma unroll
        for (int r = 0; r < ROWS_PER_WARP; r++) {
            if (!act[r]) continue;
            int s = s0 + r;

            // mid: t = p0 + s  (always valid)
            {
                float4* op = reinterpret_cast<float4*>(out_n + (size_t)(p0 + s) * F_DIM) + lane;
                __stcs(op,      val[r][0]);
                __stcs(op + 32, val[r][1]);
            }
            // left reflect: t = p0 - s, valid for 1 <= s <= p0
            if (s >= 1 && s <= p0) {
                float4* op = reinterpret_cast<float4*>(out_n + (size_t)(p0 - s) * F_DIM) + lane;
                __stcs(op,      val[r][0]);
                __stcs(op + 32, val[r][1]);
            }
            // right reflect: t = 2*lens + p0 - 2 - s, valid for lens-p1-1 <= s <= lens-2
            if (s >= lens - p1 - 1 && s <= lens - 2) {
                float4* op = reinterpret_cast<float4*>(out_n + (size_t)(2 * lens + p0 - 2 - s) * F_DIM) + lane;
                __stcs(op,      val[r][0]);
                __stcs(op + 32, val[r][1]);
            }
        }
    } else {
        // ── zero partition: t in [out_len, TP) ──
        const int t0 = (blockIdx.x - SRC_BLOCKS) * ROWS_PER_BLK + w * ROWS_PER_WARP;
        const float4 z = make_float4(0.f, 0.f, 0.f, 0.f);
        #pragma unroll
        for (int r = 0; r < ROWS_PER_WARP; r++) {
            int t = t0 + r;
            if (t < TP && t >= out_len) {
                float4* op = reinterpret_cast<float4*>(out_n + (size_t)t * F_DIM) + lane;
                __stcs(op,      z);
                __stcs(op + 32, z);
            }
        }
    }

    // Fold out_lens tail write into the first block (values exact in fp32).
    if (blockIdx.x == 0 && blockIdx.y == 0 && threadIdx.x < 16) {
        int ix = threadIdx.x;
        if (ix < tail_count) {
            int ol = __ldg(&in_lens[ix]) + __ldg(&pad[ix]) + __ldg(&pad[N_B + ix]);
            out[OUT_ELEMS + ix] = (float)ol;
        }
    }
}

extern "C" void kernel_launch(void* const* d_in, const int* in_sizes, int n_in,
                              void* d_out, int out_size)
{
    const float* in_  = (const float*)d_in[0];
    const int*   lens = (const int*)d_in[1];
    const int*   pad  = (const int*)d_in[2];
    float*       out  = (float*)d_out;

    int tail = out_size - OUT_ELEMS;   // out_lens packed after main tensor (if present)
    if (tail < 0) tail = 0;

    dim3 grid(GRID_X, N_B, 1);         // 666 x 16 = 10656 blocks
    random_shift_kernel<<<grid, 256>>>(in_, lens, pad, out, tail);
}